// round 4
// baseline (speedup 1.0000x reference)
#include <cuda_runtime.h>
#include <cuda_fp16.h>
#include <cstdint>

#define HDIM     128
#define NS       64
#define NRAYS    16384
#define NTILES   8192      // (NRAYS*64)/128 samples per tile
#define NTHREADS 256

// ---------------- shared memory layout (bytes) ----------------
#define SM_WTOT    0       // 4 floats (warp scan totals)
#define SM_PART    16      // 4 warps x 4 floats
#define SM_B3      96      // 4 floats
#define SM_B2      112     // 128 floats
#define SM_W3      640     // 128 x float4
#define SM_O1      2688    // 2*128 floats
#define SM_D1      3712    // 2*128 floats
#define SM_REND    4736    // 128 x 2 x float4 = 4096
#define SM_BH      8832    // W2^T hi fp16, pitch 136 halves: 128*272 = 34816
#define SM_BL      43648   // W2^T lo fp16, same layout
#define SMEM_TOTAL (43648 + 34816)

#define B_PITCH_B  272     // bytes per n-row (136 halves) -> conflict-free ldmatrix

static __device__ __forceinline__ uint32_t smem_u32(const void* p) {
    uint32_t a;
    asm("{ .reg .u64 t; cvta.to.shared.u64 t, %1; cvt.u32.u64 %0, t; }" : "=r"(a) : "l"(p));
    return a;
}

// decode scalar that may arrive as int32 or float32 bits
static __device__ __forceinline__ float decode_scalar(const int* p) {
    int v = *p;
    if (v >= -1000000 && v <= 1000000) return (float)v;
    return __int_as_float(v);
}

// h = relu(o + t*d) for two columns; return packed fp16x2 hi and lo (residual)
static __device__ __forceinline__ void pack_h1_split(float o0, float d0, float o1v, float d1v,
                                                     float t, uint32_t& hi, uint32_t& lo) {
    float h0 = fmaxf(fmaf(t, d0, o0), 0.0f);
    float h1 = fmaxf(fmaf(t, d1v, o1v), 0.0f);
    __half2 hh = __floats2half2_rn(h0, h1);
    float2 hf = __half22float2(hh);
    __half2 hl = __floats2half2_rn(h0 - hf.x, h1 - hf.y);
    hi = *(uint32_t*)&hh;
    lo = *(uint32_t*)&hl;
}

#define MMA16816(D, A0, A1, A2, A3, B0, B1) \
    asm volatile("mma.sync.aligned.m16n8k16.row.col.f32.f16.f16.f32 " \
                 "{%0,%1,%2,%3}, {%4,%5,%6,%7}, {%8,%9}, {%0,%1,%2,%3};" \
                 : "+f"((D)[0]), "+f"((D)[1]), "+f"((D)[2]), "+f"((D)[3]) \
                 : "r"(A0), "r"(A1), "r"(A2), "r"(A3), "r"(B0), "r"(B1))

#define LDSM_X4(R0, R1, R2, R3, ADDR) \
    asm volatile("ldmatrix.sync.aligned.m8n8.x4.shared.b16 {%0,%1,%2,%3}, [%4];" \
                 : "=r"(R0), "=r"(R1), "=r"(R2), "=r"(R3) : "r"(ADDR))

__global__ void __launch_bounds__(NTHREADS, 2)
nerf_fused_kernel(const float* __restrict__ origins, const float* __restrict__ dirs,
                  const float* __restrict__ W1, const float* __restrict__ b1,
                  const float* __restrict__ W2, const float* __restrict__ b2,
                  const float* __restrict__ W3, const float* __restrict__ b3,
                  const int* __restrict__ nearp, const int* __restrict__ farp,
                  const int* __restrict__ nsp,
                  float* __restrict__ out)
{
    extern __shared__ char smem[];
    const uint32_t smem_base = smem_u32(smem);
    const int tid = threadIdx.x;
    const int wid = tid >> 5;
    const int lid = tid & 31;

    float* wtot = (float*)(smem + SM_WTOT);
    float* part = (float*)(smem + SM_PART);
    float* b3s  = (float*)(smem + SM_B3);
    float* b2s  = (float*)(smem + SM_B2);
    float* o1s  = (float*)(smem + SM_O1);
    float* d1s  = (float*)(smem + SM_D1);
    float4* rend2 = (float4*)(smem + SM_REND);   // [row][cg]

    // ---- one-time fills ----
    if (tid < HDIM) {
        b2s[tid] = b2[tid];
        ((float4*)(smem + SM_W3))[tid] = ((const float4*)W3)[tid];
    }
    if (tid < 4) b3s[tid] = b3[tid];

    // B tiles: Bsm[n][k] = fp16 split of W2[k][n]; pitch 136 halves (272B)
    for (int i = tid; i < HDIM * HDIM; i += NTHREADS) {
        int k = i >> 7, n = i & 127;
        float w = W2[i];
        __half hh = __float2half_rn(w);
        __half hl = __float2half_rn(w - __half2float(hh));
        *(__half*)(smem + SM_BH + n * B_PITCH_B + k * 2) = hh;
        *(__half*)(smem + SM_BL + n * B_PITCH_B + k * 2) = hl;
    }

    const float nearf = decode_scalar(nearp);
    const float farf  = decode_scalar(farp);
    const float delta = (farf - nearf) * (1.0f / (float)NS);

    // warp decomposition: rg = row group (32 rows), cg = col half (64 cols)
    const int q   = lid >> 2;            // 0..7
    const int tq  = lid & 3;             // 0..3
    const int rg  = wid & 3;
    const int cg  = wid >> 2;
    const int rowq = rg * 32 + q;        // row for a0 of ms=0
    const int s0   = rowq & 63;          // sample index within ray
    const float t00 = fmaf((float)s0 + 0.5f, delta, nearf);   // ms0 row q
    const float t01 = t00 + 8.0f  * delta;                    // ms0 row q+8
    const float t10 = t00 + 16.0f * delta;                    // ms1 row q
    const float t11 = t00 + 24.0f * delta;                    // ms1 row q+8
    const int rayslot = rg >> 1;
    const float* o1ray = o1s + rayslot * HDIM;
    const float* d1ray = d1s + rayslot * HDIM;

    // ldmatrix lane offset within a 16-row n-block
    const uint32_t lm_off = (uint32_t)(((lid & 7) + ((lid >> 4) & 1) * 8) * B_PITCH_B)
                          + (uint32_t)(((lid >> 3) & 1) * 16);
    const uint32_t colbase = (uint32_t)(cg * 64) * B_PITCH_B;
    const uint32_t lm_hi = smem_base + SM_BH + colbase + lm_off;
    const uint32_t lm_lo = smem_base + SM_BL + colbase + lm_off;

    __syncthreads();

    for (int tile = blockIdx.x; tile < NTILES; tile += gridDim.x) {
        // ---- per-ray layer-1: o1 = o@W1 + b1, d1 = d@W1 (thread j = column) ----
        if (tid < HDIM) {
            int j = tid;
            float w0 = W1[j], w1v = W1[HDIM + j], w2v = W1[2 * HDIM + j], bb = b1[j];
            #pragma unroll
            for (int r = 0; r < 2; r++) {
                int ray = tile * 2 + r;
                float ox = origins[ray * 3 + 0], oy = origins[ray * 3 + 1], oz = origins[ray * 3 + 2];
                float dx = dirs[ray * 3 + 0],    dy = dirs[ray * 3 + 1],    dz = dirs[ray * 3 + 2];
                o1s[r * HDIM + j] = fmaf(ox, w0, fmaf(oy, w1v, fmaf(oz, w2v, bb)));
                d1s[r * HDIM + j] = fmaf(dx, w0, fmaf(dy, w1v, dz * w2v));
            }
        }
        __syncthreads();

        // ---- layer-2 GEMM (error-compensated fp16): warp tile m32 x n64 ----
        // acc[bg*16 + ms*8 + half*4 + i]
        float acc[64];
        #pragma unroll
        for (int i = 0; i < 64; i++) acc[i] = 0.0f;

        #pragma unroll
        for (int ks = 0; ks < 8; ks++) {
            const int c = ks * 16 + 2 * tq;
            float2 olo = *(const float2*)(o1ray + c);
            float2 dlo = *(const float2*)(d1ray + c);
            float2 ohi = *(const float2*)(o1ray + c + 8);
            float2 dhi = *(const float2*)(d1ray + c + 8);
            // ms=0 fragments
            uint32_t xh0, xl0, xh1, xl1, xh2, xl2, xh3, xl3;
            pack_h1_split(olo.x, dlo.x, olo.y, dlo.y, t00, xh0, xl0);
            pack_h1_split(olo.x, dlo.x, olo.y, dlo.y, t01, xh1, xl1);
            pack_h1_split(ohi.x, dhi.x, ohi.y, dhi.y, t00, xh2, xl2);
            pack_h1_split(ohi.x, dhi.x, ohi.y, dhi.y, t01, xh3, xl3);
            // ms=1 fragments
            uint32_t yh0, yl0, yh1, yl1, yh2, yl2, yh3, yl3;
            pack_h1_split(olo.x, dlo.x, olo.y, dlo.y, t10, yh0, yl0);
            pack_h1_split(olo.x, dlo.x, olo.y, dlo.y, t11, yh1, yl1);
            pack_h1_split(ohi.x, dhi.x, ohi.y, dhi.y, t10, yh2, yl2);
            pack_h1_split(ohi.x, dhi.x, ohi.y, dhi.y, t11, yh3, yl3);

            #pragma unroll
            for (int bg = 0; bg < 4; bg++) {
                const uint32_t toff = (uint32_t)(bg * 16 * B_PITCH_B) + (uint32_t)(ks * 32);
                uint32_t bh0, bh1, bh2, bh3, bl0v, bl1v, bl2v, bl3v;
                LDSM_X4(bh0, bh1, bh2, bh3, lm_hi + toff);
                LDSM_X4(bl0v, bl1v, bl2v, bl3v, lm_lo + toff);
                float* dA = acc + bg * 16;        // ms0, n-lo8
                float* dB = acc + bg * 16 + 4;    // ms0, n-hi8
                float* dC = acc + bg * 16 + 8;    // ms1, n-lo8
                float* dD = acc + bg * 16 + 12;   // ms1, n-hi8
                MMA16816(dA, xh0, xh1, xh2, xh3, bh0, bh1);
                MMA16816(dB, xh0, xh1, xh2, xh3, bh2, bh3);
                MMA16816(dC, yh0, yh1, yh2, yh3, bh0, bh1);
                MMA16816(dD, yh0, yh1, yh2, yh3, bh2, bh3);
                MMA16816(dA, xh0, xh1, xh2, xh3, bl0v, bl1v);
                MMA16816(dB, xh0, xh1, xh2, xh3, bl2v, bl3v);
                MMA16816(dC, yh0, yh1, yh2, yh3, bl0v, bl1v);
                MMA16816(dD, yh0, yh1, yh2, yh3, bl2v, bl3v);
                MMA16816(dA, xl0, xl1, xl2, xl3, bh0, bh1);
                MMA16816(dB, xl0, xl1, xl2, xl3, bh2, bh3);
                MMA16816(dC, yl0, yl1, yl2, yl3, bh0, bh1);
                MMA16816(dD, yl0, yl1, yl2, yl3, bh2, bh3);
            }
        }

        // ---- epilogue: h2 = relu(D + b2); partial layer-3; quad reduce; per-ms ----
        #pragma unroll
        for (int ms = 0; ms < 2; ms++) {
            float pr0 = 0, pg0 = 0, pb0 = 0, ps0 = 0;
            float pr1 = 0, pg1 = 0, pb1 = 0, ps1 = 0;
            #pragma unroll
            for (int bg = 0; bg < 4; bg++) {
                #pragma unroll
                for (int half = 0; half < 2; half++) {
                    const float* a4 = acc + bg * 16 + ms * 8 + half * 4;
                    const int c0 = cg * 64 + bg * 16 + half * 8 + 2 * tq;
                    const float bb0 = b2s[c0], bb1 = b2s[c0 + 1];
                    const float4 wA = *(const float4*)(smem + SM_W3 + c0 * 16);
                    const float4 wB = *(const float4*)(smem + SM_W3 + (c0 + 1) * 16);
                    float h00 = fmaxf(a4[0] + bb0, 0.0f);
                    float h01 = fmaxf(a4[1] + bb1, 0.0f);
                    float h10 = fmaxf(a4[2] + bb0, 0.0f);
                    float h11 = fmaxf(a4[3] + bb1, 0.0f);
                    pr0 = fmaf(h00, wA.x, fmaf(h01, wB.x, pr0));
                    pg0 = fmaf(h00, wA.y, fmaf(h01, wB.y, pg0));
                    pb0 = fmaf(h00, wA.z, fmaf(h01, wB.z, pb0));
                    ps0 = fmaf(h00, wA.w, fmaf(h01, wB.w, ps0));
                    pr1 = fmaf(h10, wA.x, fmaf(h11, wB.x, pr1));
                    pg1 = fmaf(h10, wA.y, fmaf(h11, wB.y, pg1));
                    pb1 = fmaf(h10, wA.z, fmaf(h11, wB.z, pb1));
                    ps1 = fmaf(h10, wA.w, fmaf(h11, wB.w, ps1));
                }
            }
            #pragma unroll
            for (int off = 1; off <= 2; off <<= 1) {
                pr0 += __shfl_xor_sync(0xffffffffu, pr0, off);
                pg0 += __shfl_xor_sync(0xffffffffu, pg0, off);
                pb0 += __shfl_xor_sync(0xffffffffu, pb0, off);
                ps0 += __shfl_xor_sync(0xffffffffu, ps0, off);
                pr1 += __shfl_xor_sync(0xffffffffu, pr1, off);
                pg1 += __shfl_xor_sync(0xffffffffu, pg1, off);
                pb1 += __shfl_xor_sync(0xffffffffu, pb1, off);
                ps1 += __shfl_xor_sync(0xffffffffu, ps1, off);
            }
            if (tq == 0) {
                const int r = rg * 32 + ms * 16 + q;
                rend2[r * 2 + cg]       = make_float4(pr0, pg0, pb0, ps0);
                rend2[(r + 8) * 2 + cg] = make_float4(pr1, pg1, pb1, ps1);
            }
        }
        __syncthreads();

        // ---- volume rendering: exact log-space scan (thread = sample, tid<128) ----
        if (tid < 128) {
            float4 fa = rend2[tid * 2 + 0];
            float4 fb = rend2[tid * 2 + 1];
            float fx = fa.x + fb.x, fy = fa.y + fb.y, fz = fa.z + fb.z, fw = fa.w + fb.w;
            float sd = (fw + b3s[3]) * delta;

            float x = sd;
            #pragma unroll
            for (int off = 1; off < 32; off <<= 1) {
                float v = __shfl_up_sync(0xffffffffu, x, off);
                if (lid >= off) x += v;
            }
            if (lid == 31) wtot[wid] = x;
            rend2[tid * 2 + 0] = make_float4(fx, fy, fz, x);   // stash colors + inclusive scan
        }
        __syncthreads();
        if (tid < 128) {
            float4 f = rend2[tid * 2 + 0];
            float cr = f.x + b3s[0], cg2 = f.y + b3s[1], cb = f.z + b3s[2];
            float x  = f.w;              // inclusive scan of sd within warp
            float prev = __shfl_up_sync(0xffffffffu, x, 1);
            float sd = (lid > 0) ? (x - prev) : x;
            float pre = x - sd;
            if (wid & 1) pre += wtot[wid & ~1];
            float w = __expf(-pre) - __expf(-(pre + sd));

            float wr = w * cr, wg = w * cg2, wb = w * cb;
            #pragma unroll
            for (int off = 16; off > 0; off >>= 1) {
                wr += __shfl_down_sync(0xffffffffu, wr, off);
                wg += __shfl_down_sync(0xffffffffu, wg, off);
                wb += __shfl_down_sync(0xffffffffu, wb, off);
            }
            if (lid == 0) {
                float* p = part + wid * 4;
                p[0] = wr; p[1] = wg; p[2] = wb;
            }
        }
        __syncthreads();
        if (tid < 2) {
            const float* p0 = part + tid * 8;   // warps {2t, 2t+1}
            int ray = tile * 2 + tid;
            out[ray * 3 + 0] = p0[0] + p0[4];
            out[ray * 3 + 1] = p0[1] + p0[5];
            out[ray * 3 + 2] = p0[2] + p0[6];
        }
        __syncthreads();
    }
}

extern "C" void kernel_launch(void* const* d_in, const int* in_sizes, int n_in,
                              void* d_out, int out_size) {
    (void)in_sizes; (void)n_in; (void)out_size;
    const float* origins = (const float*)d_in[0];
    const float* dirs    = (const float*)d_in[1];
    const float* W1      = (const float*)d_in[2];
    const float* b1      = (const float*)d_in[3];
    const float* W2      = (const float*)d_in[4];
    const float* b2      = (const float*)d_in[5];
    const float* W3      = (const float*)d_in[6];
    const float* b3      = (const float*)d_in[7];
    const int*   nearp   = (const int*)d_in[8];
    const int*   farp    = (const int*)d_in[9];
    const int*   nsp     = (const int*)d_in[10];
    float* out = (float*)d_out;

    int sms = 0;
    cudaDeviceGetAttribute(&sms, cudaDevAttrMultiProcessorCount, 0);
    if (sms <= 0) sms = 148;
    int grid = sms * 2;                 // persistent: 2 CTAs/SM
    if (grid > NTILES) grid = NTILES;

    cudaFuncSetAttribute(nerf_fused_kernel,
                         cudaFuncAttributeMaxDynamicSharedMemorySize, SMEM_TOTAL);
    nerf_fused_kernel<<<grid, NTHREADS, SMEM_TOTAL>>>(
        origins, dirs, W1, b1, W2, b2, W3, b3, nearp, farp, nsp, out);
}

// round 6
// speedup vs baseline: 1.0641x; 1.0641x over previous
#include <cuda_runtime.h>
#include <cuda_fp16.h>
#include <cstdint>

#define HDIM     128
#define NS       64
#define NRAYS    16384
#define NTILES   8192      // (NRAYS*64)/128 samples per tile
#define NTHREADS 256

// ---------------- shared memory layout (bytes) ----------------
#define SM_WTOT    0       // 4 floats (warp scan totals)
#define SM_PART    16      // 4 warps x 4 floats
#define SM_B3      96      // 4 floats
#define SM_B2      112     // 128 floats
#define SM_W3      640     // 128 x float4
#define SM_O1      2688    // 2*128 floats
#define SM_D1      3712    // 2*128 floats
#define SM_REND    4736    // 128 x float4
#define SM_BH      6912    // W2^T hi fp16, pitch 136 halves: 128*272 = 34816
#define SM_BL      41728   // W2^T lo fp16, same layout
#define SMEM_TOTAL (41728 + 34816)

#define B_PITCH_B  272     // bytes per n-row (136 halves) -> conflict-free ldmatrix

static __device__ __forceinline__ uint32_t smem_u32(const void* p) {
    uint32_t a;
    asm("{ .reg .u64 t; cvta.to.shared.u64 t, %1; cvt.u32.u64 %0, t; }" : "=r"(a) : "l"(p));
    return a;
}

// decode scalar that may arrive as int32 or float32 bits
static __device__ __forceinline__ float decode_scalar(const int* p) {
    int v = *p;
    if (v >= -1000000 && v <= 1000000) return (float)v;
    return __int_as_float(v);
}

// h = relu(o + t*d) for two columns; return packed fp16x2 hi and lo (residual)
static __device__ __forceinline__ void pack_h1_split(float o0, float d0, float o1v, float d1v,
                                                     float t, uint32_t& hi, uint32_t& lo) {
    float h0 = fmaxf(fmaf(t, d0, o0), 0.0f);
    float h1 = fmaxf(fmaf(t, d1v, o1v), 0.0f);
    __half2 hh = __floats2half2_rn(h0, h1);
    float2 hf = __half22float2(hh);
    __half2 hl = __floats2half2_rn(h0 - hf.x, h1 - hf.y);
    hi = *(uint32_t*)&hh;
    lo = *(uint32_t*)&hl;
}

#define MMA16816(D, A0, A1, A2, A3, B0, B1) \
    asm volatile("mma.sync.aligned.m16n8k16.row.col.f32.f16.f16.f32 " \
                 "{%0,%1,%2,%3}, {%4,%5,%6,%7}, {%8,%9}, {%0,%1,%2,%3};" \
                 : "+f"((D)[0]), "+f"((D)[1]), "+f"((D)[2]), "+f"((D)[3]) \
                 : "r"(A0), "r"(A1), "r"(A2), "r"(A3), "r"(B0), "r"(B1))

#define LDSM_X4(R0, R1, R2, R3, ADDR) \
    asm volatile("ldmatrix.sync.aligned.m8n8.x4.shared.b16 {%0,%1,%2,%3}, [%4];" \
                 : "=r"(R0), "=r"(R1), "=r"(R2), "=r"(R3) : "r"(ADDR))

__global__ void __launch_bounds__(NTHREADS, 2)
nerf_fused_kernel(const float* __restrict__ origins, const float* __restrict__ dirs,
                  const float* __restrict__ W1, const float* __restrict__ b1,
                  const float* __restrict__ W2, const float* __restrict__ b2,
                  const float* __restrict__ W3, const float* __restrict__ b3,
                  const int* __restrict__ nearp, const int* __restrict__ farp,
                  const int* __restrict__ nsp,
                  float* __restrict__ out)
{
    extern __shared__ char smem[];
    const uint32_t smem_base = smem_u32(smem);
    const int tid = threadIdx.x;
    const int wid = tid >> 5;
    const int lid = tid & 31;

    float* wtot = (float*)(smem + SM_WTOT);
    float* part = (float*)(smem + SM_PART);
    float* b3s  = (float*)(smem + SM_B3);
    float* b2s  = (float*)(smem + SM_B2);
    float* o1s  = (float*)(smem + SM_O1);
    float* d1s  = (float*)(smem + SM_D1);
    float* rend = (float*)(smem + SM_REND);

    // ---- one-time fills ----
    if (tid < HDIM) {
        b2s[tid] = b2[tid];
        ((float4*)(smem + SM_W3))[tid] = ((const float4*)W3)[tid];
    }
    if (tid < 4) b3s[tid] = b3[tid];

    // B tiles: Bsm[n][k] = fp16 split of W2[k][n]; pitch 136 halves (272B)
    for (int i = tid; i < HDIM * HDIM; i += NTHREADS) {
        int k = i >> 7, n = i & 127;
        float w = W2[i];
        __half hh = __float2half_rn(w);
        __half hl = __float2half_rn(w - __half2float(hh));
        *(__half*)(smem + SM_BH + n * B_PITCH_B + k * 2) = hh;
        *(__half*)(smem + SM_BL + n * B_PITCH_B + k * 2) = hl;
    }

    const float nearf = decode_scalar(nearp);
    const float farf  = decode_scalar(farp);
    const float delta = (farf - nearf) * (1.0f / (float)NS);

    // per-thread constants for the mma slice (warp tile m16 x n128)
    const int q        = lid >> 2;                 // 0..7 row group
    const int tq       = lid & 3;                  // 0..3 col quad
    const int r0       = wid * 16 + q;             // global sample row (0..127)
    const int s0       = r0 & 63;
    const float t0     = fmaf((float)s0 + 0.5f, delta, nearf);
    const float t1     = t0 + 8.0f * delta;
    const int rayslot  = wid >> 2;                 // ray within tile for this warp
    const float* o1ray = o1s + rayslot * HDIM;
    const float* d1ray = d1s + rayslot * HDIM;

    // ldmatrix lane offset within a B tile
    const uint32_t lm_off = (uint32_t)(((lid & 7) + ((lid >> 4) & 1) * 8) * B_PITCH_B)
                          + (uint32_t)(((lid >> 3) & 1) * 16);
    const uint32_t lm_hi = smem_base + SM_BH + lm_off;
    const uint32_t lm_lo = smem_base + SM_BL + lm_off;

    __syncthreads();

    for (int tile = blockIdx.x; tile < NTILES; tile += gridDim.x) {
        // ---- per-ray layer-1: o1 = o@W1 + b1, d1 = d@W1 (thread j = column) ----
        if (tid < HDIM) {
            int j = tid;
            float w0 = W1[j], w1v = W1[HDIM + j], w2v = W1[2 * HDIM + j], bb = b1[j];
            #pragma unroll
            for (int r = 0; r < 2; r++) {
                int ray = tile * 2 + r;
                float ox = origins[ray * 3 + 0], oy = origins[ray * 3 + 1], oz = origins[ray * 3 + 2];
                float dx = dirs[ray * 3 + 0],    dy = dirs[ray * 3 + 1],    dz = dirs[ray * 3 + 2];
                o1s[r * HDIM + j] = fmaf(ox, w0, fmaf(oy, w1v, fmaf(oz, w2v, bb)));
                d1s[r * HDIM + j] = fmaf(dx, w0, fmaf(dy, w1v, dz * w2v));
            }
        }
        __syncthreads();

        // ---- layer-2 GEMM (error-compensated fp16): rows [wid*16,+16) x 128 cols ----
        // ntp processed in pairs; 12 MMAs round-robin over 4 independent acc groups.
        float acc[64];
        #pragma unroll
        for (int i = 0; i < 64; i++) acc[i] = 0.0f;

        #pragma unroll
        for (int ks = 0; ks < 8; ks++) {
            const int c = ks * 16 + 2 * tq;
            float2 olo = *(const float2*)(o1ray + c);
            float2 dlo = *(const float2*)(d1ray + c);
            float2 ohi = *(const float2*)(o1ray + c + 8);
            float2 dhi = *(const float2*)(d1ray + c + 8);
            uint32_t ah0, al0, ah1, al1, ah2, al2, ah3, al3;
            pack_h1_split(olo.x, dlo.x, olo.y, dlo.y, t0, ah0, al0);
            pack_h1_split(olo.x, dlo.x, olo.y, dlo.y, t1, ah1, al1);
            pack_h1_split(ohi.x, dhi.x, ohi.y, dhi.y, t0, ah2, al2);
            pack_h1_split(ohi.x, dhi.x, ohi.y, dhi.y, t1, ah3, al3);

            #pragma unroll
            for (int np = 0; np < 4; np++) {
                const uint32_t toff0 = (uint32_t)((2 * np) * 16 * B_PITCH_B) + (uint32_t)(ks * 32);
                const uint32_t toff1 = toff0 + (uint32_t)(16 * B_PITCH_B);
                uint32_t h00, h01, h02, h03, h10, h11, h12, h13;
                uint32_t l00, l01, l02, l03, l10, l11, l12, l13;
                LDSM_X4(h00, h01, h02, h03, lm_hi + toff0);
                LDSM_X4(h10, h11, h12, h13, lm_hi + toff1);
                LDSM_X4(l00, l01, l02, l03, lm_lo + toff0);
                LDSM_X4(l10, l11, l12, l13, lm_lo + toff1);
                float* dA0 = acc + (2 * np) * 8;
                float* dB0 = dA0 + 4;
                float* dA1 = acc + (2 * np + 1) * 8;
                float* dB1 = dA1 + 4;
                // chain 1: Ah * Bh
                MMA16816(dA0, ah0, ah1, ah2, ah3, h00, h01);
                MMA16816(dA1, ah0, ah1, ah2, ah3, h10, h11);
                MMA16816(dB0, ah0, ah1, ah2, ah3, h02, h03);
                MMA16816(dB1, ah0, ah1, ah2, ah3, h12, h13);
                // chain 2: Ah * Bl
                MMA16816(dA0, ah0, ah1, ah2, ah3, l00, l01);
                MMA16816(dA1, ah0, ah1, ah2, ah3, l10, l11);
                MMA16816(dB0, ah0, ah1, ah2, ah3, l02, l03);
                MMA16816(dB1, ah0, ah1, ah2, ah3, l12, l13);
                // chain 3: Al * Bh
                MMA16816(dA0, al0, al1, al2, al3, h00, h01);
                MMA16816(dA1, al0, al1, al2, al3, h10, h11);
                MMA16816(dB0, al0, al1, al2, al3, h02, h03);
                MMA16816(dB1, al0, al1, al2, al3, h12, h13);
            }
        }

        // ---- epilogue: h2 = relu(D + b2); partial layer-3; quad reduce ----
        float pr0 = 0, pg0 = 0, pb0 = 0, ps0 = 0;
        float pr1 = 0, pg1 = 0, pb1 = 0, ps1 = 0;
        #pragma unroll
        for (int nt = 0; nt < 16; nt++) {
            const int c0 = nt * 8 + 2 * tq;
            const float bb0 = b2s[c0], bb1 = b2s[c0 + 1];
            const float4 wA = *(const float4*)(smem + SM_W3 + c0 * 16);
            const float4 wB = *(const float4*)(smem + SM_W3 + (c0 + 1) * 16);
            // acc layout: nt even -> acc[(nt/2)*8 + 0..3], nt odd -> acc[(nt/2)*8 + 4..7]
            const float* a4 = acc + (nt >> 1) * 8 + (nt & 1) * 4;
            float h00 = fmaxf(a4[0] + bb0, 0.0f);
            float h01 = fmaxf(a4[1] + bb1, 0.0f);
            float h10 = fmaxf(a4[2] + bb0, 0.0f);
            float h11 = fmaxf(a4[3] + bb1, 0.0f);
            pr0 = fmaf(h00, wA.x, fmaf(h01, wB.x, pr0));
            pg0 = fmaf(h00, wA.y, fmaf(h01, wB.y, pg0));
            pb0 = fmaf(h00, wA.z, fmaf(h01, wB.z, pb0));
            ps0 = fmaf(h00, wA.w, fmaf(h01, wB.w, ps0));
            pr1 = fmaf(h10, wA.x, fmaf(h11, wB.x, pr1));
            pg1 = fmaf(h10, wA.y, fmaf(h11, wB.y, pg1));
            pb1 = fmaf(h10, wA.z, fmaf(h11, wB.z, pb1));
            ps1 = fmaf(h10, wA.w, fmaf(h11, wB.w, ps1));
        }
        #pragma unroll
        for (int off = 1; off <= 2; off <<= 1) {
            pr0 += __shfl_xor_sync(0xffffffffu, pr0, off);
            pg0 += __shfl_xor_sync(0xffffffffu, pg0, off);
            pb0 += __shfl_xor_sync(0xffffffffu, pb0, off);
            ps0 += __shfl_xor_sync(0xffffffffu, ps0, off);
            pr1 += __shfl_xor_sync(0xffffffffu, pr1, off);
            pg1 += __shfl_xor_sync(0xffffffffu, pg1, off);
            pb1 += __shfl_xor_sync(0xffffffffu, pb1, off);
            ps1 += __shfl_xor_sync(0xffffffffu, ps1, off);
        }
        if (tq == 0) {
            ((float4*)rend)[r0]     = make_float4(pr0, pg0, pb0, ps0);
            ((float4*)rend)[r0 + 8] = make_float4(pr1, pg1, pb1, ps1);
        }
        __syncthreads();

        // ---- volume rendering: exact log-space scan; state held in registers ----
        float cr = 0, cg = 0, cb = 0, sd = 0, x = 0;
        if (tid < 128) {
            float4 f = ((const float4*)rend)[tid];
            cr = f.x + b3s[0]; cg = f.y + b3s[1]; cb = f.z + b3s[2];
            sd = (f.w + b3s[3]) * delta;

            x = sd;
            #pragma unroll
            for (int off = 1; off < 32; off <<= 1) {
                float v = __shfl_up_sync(0xffffffffu, x, off);
                if (lid >= off) x += v;
            }
            if (lid == 31) wtot[wid] = x;
        }
        __syncthreads();
        if (tid < 128) {
            float pre = x - sd;
            if (wid & 1) pre += wtot[wid & ~1];
            float w = __expf(-pre) - __expf(-(pre + sd));

            float wr = w * cr, wg = w * cg, wb = w * cb;
            #pragma unroll
            for (int off = 16; off > 0; off >>= 1) {
                wr += __shfl_down_sync(0xffffffffu, wr, off);
                wg += __shfl_down_sync(0xffffffffu, wg, off);
                wb += __shfl_down_sync(0xffffffffu, wb, off);
            }
            if (lid == 0) {
                float* p = part + wid * 4;
                p[0] = wr; p[1] = wg; p[2] = wb;
            }
        }
        __syncthreads();
        if (tid < 2) {
            const float* p0 = part + tid * 8;   // warps {2t, 2t+1}
            int ray = tile * 2 + tid;
            out[ray * 3 + 0] = p0[0] + p0[4];
            out[ray * 3 + 1] = p0[1] + p0[5];
            out[ray * 3 + 2] = p0[2] + p0[6];
        }
        // no trailing sync needed: part/wtot/rend are next written only after
        // at least one intervening __syncthreads (epilogue sync of next tile).
    }
}

extern "C" void kernel_launch(void* const* d_in, const int* in_sizes, int n_in,
                              void* d_out, int out_size) {
    (void)in_sizes; (void)n_in; (void)out_size;
    const float* origins = (const float*)d_in[0];
    const float* dirs    = (const float*)d_in[1];
    const float* W1      = (const float*)d_in[2];
    const float* b1      = (const float*)d_in[3];
    const float* W2      = (const float*)d_in[4];
    const float* b2      = (const float*)d_in[5];
    const float* W3      = (const float*)d_in[6];
    const float* b3      = (const float*)d_in[7];
    const int*   nearp   = (const int*)d_in[8];
    const int*   farp    = (const int*)d_in[9];
    const int*   nsp     = (const int*)d_in[10];
    float* out = (float*)d_out;

    int sms = 0;
    cudaDeviceGetAttribute(&sms, cudaDevAttrMultiProcessorCount, 0);
    if (sms <= 0) sms = 148;
    int grid = sms * 2;                 // persistent: 2 CTAs/SM (RF-limited)
    if (grid > NTILES) grid = NTILES;

    cudaFuncSetAttribute(nerf_fused_kernel,
                         cudaFuncAttributeMaxDynamicSharedMemorySize, SMEM_TOTAL);
    nerf_fused_kernel<<<grid, NTHREADS, SMEM_TOTAL>>>(
        origins, dirs, W1, b1, W2, b2, W3, b3, nearp, farp, nsp, out);
}

// round 8
// speedup vs baseline: 1.3516x; 1.2702x over previous
#include <cuda_runtime.h>
#include <cuda_fp16.h>
#include <cstdint>

#define HDIM     128
#define NS       64
#define NRAYS    16384
#define NTILES   8192      // (NRAYS*64)/128 samples per tile
#define NTHREADS 256

// ---------------- shared memory layout (bytes) ----------------
#define SM_WTOT    0       // 4 floats (warp scan totals)
#define SM_PART    16      // 4 warps x 4 floats
#define SM_B3      96      // 4 floats
#define SM_B2      112     // 128 floats
#define SM_W3      640     // 128 x float4
#define SM_O1      2688    // 2*128 floats
#define SM_D1      3712    // 2*128 floats
#define SM_REND    4736    // 128 x float4
#define SM_BH      6912    // W2^T hi fp16, pitch 136 halves: 128*272 = 34816
#define SM_BL      41728   // W2^T lo fp16 (residual), same layout
#define SMEM_TOTAL (41728 + 34816)

#define B_PITCH_B  272     // bytes per n-row (136 halves) -> conflict-free ldmatrix

static __device__ __forceinline__ uint32_t smem_u32(const void* p) {
    uint32_t a;
    asm("{ .reg .u64 t; cvta.to.shared.u64 t, %1; cvt.u32.u64 %0, t; }" : "=r"(a) : "l"(p));
    return a;
}

// decode scalar that may arrive as int32 or float32 bits
static __device__ __forceinline__ float decode_scalar(const int* p) {
    int v = *p;
    if (v >= -1000000 && v <= 1000000) return (float)v;
    return __int_as_float(v);
}

// h = relu(o + t*d) for two columns; packed fp16x2 (no residual — A-side error
// measured negligible: R7 showed dropping Al*Bh changes rel_err 1.437e-3 -> 1.405e-3)
static __device__ __forceinline__ uint32_t pack_h1(float o0, float d0, float o1v, float d1v,
                                                   float t) {
    float h0 = fmaxf(fmaf(t, d0, o0), 0.0f);
    float h1 = fmaxf(fmaf(t, d1v, o1v), 0.0f);
    __half2 hh = __floats2half2_rn(h0, h1);
    return *(uint32_t*)&hh;
}

#define MMA16816(D, A0, A1, A2, A3, B0, B1) \
    asm volatile("mma.sync.aligned.m16n8k16.row.col.f32.f16.f16.f32 " \
                 "{%0,%1,%2,%3}, {%4,%5,%6,%7}, {%8,%9}, {%0,%1,%2,%3};" \
                 : "+f"((D)[0]), "+f"((D)[1]), "+f"((D)[2]), "+f"((D)[3]) \
                 : "r"(A0), "r"(A1), "r"(A2), "r"(A3), "r"(B0), "r"(B1))

#define LDSM_X4(R0, R1, R2, R3, ADDR) \
    asm volatile("ldmatrix.sync.aligned.m8n8.x4.shared.b16 {%0,%1,%2,%3}, [%4];" \
                 : "=r"(R0), "=r"(R1), "=r"(R2), "=r"(R3) : "r"(ADDR))

__global__ void __launch_bounds__(NTHREADS, 2)
nerf_fused_kernel(const float* __restrict__ origins, const float* __restrict__ dirs,
                  const float* __restrict__ W1, const float* __restrict__ b1,
                  const float* __restrict__ W2, const float* __restrict__ b2,
                  const float* __restrict__ W3, const float* __restrict__ b3,
                  const int* __restrict__ nearp, const int* __restrict__ farp,
                  const int* __restrict__ nsp,
                  float* __restrict__ out)
{
    extern __shared__ char smem[];
    const uint32_t smem_base = smem_u32(smem);
    const int tid = threadIdx.x;
    const int wid = tid >> 5;
    const int lid = tid & 31;

    float* wtot = (float*)(smem + SM_WTOT);
    float* part = (float*)(smem + SM_PART);
    float* b3s  = (float*)(smem + SM_B3);
    float* b2s  = (float*)(smem + SM_B2);
    float* o1s  = (float*)(smem + SM_O1);
    float* d1s  = (float*)(smem + SM_D1);
    float* rend = (float*)(smem + SM_REND);

    // ---- one-time fills ----
    if (tid < HDIM) {
        b2s[tid] = b2[tid];
        ((float4*)(smem + SM_W3))[tid] = ((const float4*)W3)[tid];
    }
    if (tid < 4) b3s[tid] = b3[tid];

    // B tiles: Bsm[n][k] = fp16 split of W2[k][n]; pitch 136 halves (272B)
    for (int i = tid; i < HDIM * HDIM; i += NTHREADS) {
        int k = i >> 7, n = i & 127;
        float w = W2[i];
        __half hh = __float2half_rn(w);
        __half hl = __float2half_rn(w - __half2float(hh));
        *(__half*)(smem + SM_BH + n * B_PITCH_B + k * 2) = hh;
        *(__half*)(smem + SM_BL + n * B_PITCH_B + k * 2) = hl;
    }

    const float nearf = decode_scalar(nearp);
    const float farf  = decode_scalar(farp);
    const float delta = (farf - nearf) * (1.0f / (float)NS);

    // per-thread constants for the mma slice (warp tile m16 x n128)
    const int q        = lid >> 2;                 // 0..7 row group
    const int tq       = lid & 3;                  // 0..3 col quad
    const int r0       = wid * 16 + q;             // global sample row (0..127)
    const int s0       = r0 & 63;
    const float t0     = fmaf((float)s0 + 0.5f, delta, nearf);
    const float t1     = t0 + 8.0f * delta;
    const int rayslot  = wid >> 2;                 // ray within tile for this warp
    const float* o1ray = o1s + rayslot * HDIM;
    const float* d1ray = d1s + rayslot * HDIM;

    // ldmatrix lane offset within a B tile
    const uint32_t lm_off = (uint32_t)(((lid & 7) + ((lid >> 4) & 1) * 8) * B_PITCH_B)
                          + (uint32_t)(((lid >> 3) & 1) * 16);
    const uint32_t lm_hi = smem_base + SM_BH + lm_off;
    const uint32_t lm_lo = smem_base + SM_BL + lm_off;

    __syncthreads();

    for (int tile = blockIdx.x; tile < NTILES; tile += gridDim.x) {
        // ---- per-ray layer-1: o1 = o@W1 + b1, d1 = d@W1 (thread j = column) ----
        if (tid < HDIM) {
            int j = tid;
            float w0 = W1[j], w1v = W1[HDIM + j], w2v = W1[2 * HDIM + j], bb = b1[j];
            #pragma unroll
            for (int r = 0; r < 2; r++) {
                int ray = tile * 2 + r;
                float ox = origins[ray * 3 + 0], oy = origins[ray * 3 + 1], oz = origins[ray * 3 + 2];
                float dx = dirs[ray * 3 + 0],    dy = dirs[ray * 3 + 1],    dz = dirs[ray * 3 + 2];
                o1s[r * HDIM + j] = fmaf(ox, w0, fmaf(oy, w1v, fmaf(oz, w2v, bb)));
                d1s[r * HDIM + j] = fmaf(dx, w0, fmaf(dy, w1v, dz * w2v));
            }
        }
        __syncthreads();

        // ---- layer-2 GEMM: Ah @ (Bh + Bl), 2 chains, rows [wid*16,+16) x 128 cols ----
        float acc[64];
        #pragma unroll
        for (int i = 0; i < 64; i++) acc[i] = 0.0f;

        #pragma unroll
        for (int ks = 0; ks < 8; ks++) {
            const int c = ks * 16 + 2 * tq;
            float2 olo = *(const float2*)(o1ray + c);
            float2 dlo = *(const float2*)(d1ray + c);
            float2 ohi = *(const float2*)(o1ray + c + 8);
            float2 dhi = *(const float2*)(d1ray + c + 8);
            uint32_t a0 = pack_h1(olo.x, dlo.x, olo.y, dlo.y, t0);
            uint32_t a1 = pack_h1(olo.x, dlo.x, olo.y, dlo.y, t1);
            uint32_t a2 = pack_h1(ohi.x, dhi.x, ohi.y, dhi.y, t0);
            uint32_t a3 = pack_h1(ohi.x, dhi.x, ohi.y, dhi.y, t1);

            #pragma unroll
            for (int np = 0; np < 4; np++) {
                const uint32_t toff0 = (uint32_t)((2 * np) * 16 * B_PITCH_B) + (uint32_t)(ks * 32);
                const uint32_t toff1 = toff0 + (uint32_t)(16 * B_PITCH_B);
                uint32_t h00, h01, h02, h03, h10, h11, h12, h13;
                uint32_t l00, l01, l02, l03, l10, l11, l12, l13;
                LDSM_X4(h00, h01, h02, h03, lm_hi + toff0);
                LDSM_X4(h10, h11, h12, h13, lm_hi + toff1);
                LDSM_X4(l00, l01, l02, l03, lm_lo + toff0);
                LDSM_X4(l10, l11, l12, l13, lm_lo + toff1);
                float* dA0 = acc + (2 * np) * 8;
                float* dB0 = dA0 + 4;
                float* dA1 = acc + (2 * np + 1) * 8;
                float* dB1 = dA1 + 4;
                // chain 1: Ah * Bh
                MMA16816(dA0, a0, a1, a2, a3, h00, h01);
                MMA16816(dA1, a0, a1, a2, a3, h10, h11);
                MMA16816(dB0, a0, a1, a2, a3, h02, h03);
                MMA16816(dB1, a0, a1, a2, a3, h12, h13);
                // chain 2: Ah * Bl  (B residual — the dominant error term per R7)
                MMA16816(dA0, a0, a1, a2, a3, l00, l01);
                MMA16816(dA1, a0, a1, a2, a3, l10, l11);
                MMA16816(dB0, a0, a1, a2, a3, l02, l03);
                MMA16816(dB1, a0, a1, a2, a3, l12, l13);
            }
        }

        // ---- epilogue: h2 = relu(D + b2); partial layer-3; quad reduce ----
        float pr0 = 0, pg0 = 0, pb0 = 0, ps0 = 0;
        float pr1 = 0, pg1 = 0, pb1 = 0, ps1 = 0;
        #pragma unroll
        for (int nt = 0; nt < 16; nt++) {
            const int c0 = nt * 8 + 2 * tq;
            const float bb0 = b2s[c0], bb1 = b2s[c0 + 1];
            const float4 wA = *(const float4*)(smem + SM_W3 + c0 * 16);
            const float4 wB = *(const float4*)(smem + SM_W3 + (c0 + 1) * 16);
            // acc layout: nt even -> acc[(nt/2)*8 + 0..3], nt odd -> acc[(nt/2)*8 + 4..7]
            const float* a4 = acc + (nt >> 1) * 8 + (nt & 1) * 4;
            float h00 = fmaxf(a4[0] + bb0, 0.0f);
            float h01 = fmaxf(a4[1] + bb1, 0.0f);
            float h10 = fmaxf(a4[2] + bb0, 0.0f);
            float h11 = fmaxf(a4[3] + bb1, 0.0f);
            pr0 = fmaf(h00, wA.x, fmaf(h01, wB.x, pr0));
            pg0 = fmaf(h00, wA.y, fmaf(h01, wB.y, pg0));
            pb0 = fmaf(h00, wA.z, fmaf(h01, wB.z, pb0));
            ps0 = fmaf(h00, wA.w, fmaf(h01, wB.w, ps0));
            pr1 = fmaf(h10, wA.x, fmaf(h11, wB.x, pr1));
            pg1 = fmaf(h10, wA.y, fmaf(h11, wB.y, pg1));
            pb1 = fmaf(h10, wA.z, fmaf(h11, wB.z, pb1));
            ps1 = fmaf(h10, wA.w, fmaf(h11, wB.w, ps1));
        }
        #pragma unroll
        for (int off = 1; off <= 2; off <<= 1) {
            pr0 += __shfl_xor_sync(0xffffffffu, pr0, off);
            pg0 += __shfl_xor_sync(0xffffffffu, pg0, off);
            pb0 += __shfl_xor_sync(0xffffffffu, pb0, off);
            ps0 += __shfl_xor_sync(0xffffffffu, ps0, off);
            pr1 += __shfl_xor_sync(0xffffffffu, pr1, off);
            pg1 += __shfl_xor_sync(0xffffffffu, pg1, off);
            pb1 += __shfl_xor_sync(0xffffffffu, pb1, off);
            ps1 += __shfl_xor_sync(0xffffffffu, ps1, off);
        }
        if (tq == 0) {
            ((float4*)rend)[r0]     = make_float4(pr0, pg0, pb0, ps0);
            ((float4*)rend)[r0 + 8] = make_float4(pr1, pg1, pb1, ps1);
        }
        __syncthreads();

        // ---- volume rendering: exact log-space scan; state held in registers ----
        float cr = 0, cg = 0, cb = 0, sd = 0, x = 0;
        if (tid < 128) {
            float4 f = ((const float4*)rend)[tid];
            cr = f.x + b3s[0]; cg = f.y + b3s[1]; cb = f.z + b3s[2];
            sd = (f.w + b3s[3]) * delta;

            x = sd;
            #pragma unroll
            for (int off = 1; off < 32; off <<= 1) {
                float v = __shfl_up_sync(0xffffffffu, x, off);
                if (lid >= off) x += v;
            }
            if (lid == 31) wtot[wid] = x;
        }
        __syncthreads();
        if (tid < 128) {
            float pre = x - sd;
            if (wid & 1) pre += wtot[wid & ~1];
            float w = __expf(-pre) - __expf(-(pre + sd));

            float wr = w * cr, wg = w * cg, wb = w * cb;
            #pragma unroll
            for (int off = 16; off > 0; off >>= 1) {
                wr += __shfl_down_sync(0xffffffffu, wr, off);
                wg += __shfl_down_sync(0xffffffffu, wg, off);
                wb += __shfl_down_sync(0xffffffffu, wb, off);
            }
            if (lid == 0) {
                float* p = part + wid * 4;
                p[0] = wr; p[1] = wg; p[2] = wb;
            }
        }
        __syncthreads();
        if (tid < 2) {
            const float* p0 = part + tid * 8;   // warps {2t, 2t+1}
            int ray = tile * 2 + tid;
            out[ray * 3 + 0] = p0[0] + p0[4];
            out[ray * 3 + 1] = p0[1] + p0[5];
            out[ray * 3 + 2] = p0[2] + p0[6];
        }
        // no trailing sync needed: part/wtot/rend are next written only after
        // at least one intervening __syncthreads (epilogue sync of next tile).
    }
}

extern "C" void kernel_launch(void* const* d_in, const int* in_sizes, int n_in,
                              void* d_out, int out_size) {
    (void)in_sizes; (void)n_in; (void)out_size;
    const float* origins = (const float*)d_in[0];
    const float* dirs    = (const float*)d_in[1];
    const float* W1      = (const float*)d_in[2];
    const float* b1      = (const float*)d_in[3];
    const float* W2      = (const float*)d_in[4];
    const float* b2      = (const float*)d_in[5];
    const float* W3      = (const float*)d_in[6];
    const float* b3      = (const float*)d_in[7];
    const int*   nearp   = (const int*)d_in[8];
    const int*   farp    = (const int*)d_in[9];
    const int*   nsp     = (const int*)d_in[10];
    float* out = (float*)d_out;

    int sms = 0;
    cudaDeviceGetAttribute(&sms, cudaDevAttrMultiProcessorCount, 0);
    if (sms <= 0) sms = 148;
    int grid = sms * 2;                 // persistent: 2 CTAs/SM (RF-limited)
    if (grid > NTILES) grid = NTILES;

    cudaFuncSetAttribute(nerf_fused_kernel,
                         cudaFuncAttributeMaxDynamicSharedMemorySize, SMEM_TOTAL);
    nerf_fused_kernel<<<grid, NTHREADS, SMEM_TOTAL>>>(
        origins, dirs, W1, b1, W2, b2, W3, b3, nearp, farp, nsp, out);
}